// round 16
// baseline (speedup 1.0000x reference)
#include <cuda_runtime.h>
#include <cuda_bf16.h>
#include <cstdint>

// Problem constants
#define BB 4
#define TT 2048
#define EE 1024
#define HH 16
#define DD 64
#define MM (BB*TT)                 // 8192
#define NELEM ((size_t)MM * EE)    // 8388608
#define WELEM ((size_t)EE * EE)    // 1048576

// ---------------- scratch: bf16 hi/mid planes (no runtime alloc) ----------
__device__ uint16_t g_qh [NELEM], g_qm [NELEM];   // split of input q
__device__ uint16_t g_vh [NELEM], g_vm [NELEM];   // split of input v
__device__ uint16_t g_qph[NELEM], g_qpm[NELEM];   // qp (row-major)
__device__ uint16_t g_kph[NELEM], g_kpm[NELEM];   // kp (row-major)
__device__ uint16_t g_vth[NELEM], g_vtm[NELEM];   // vp TRANSPOSED: [(b,h,d)][t]
__device__ uint16_t g_yh [NELEM], g_ym [NELEM];   // attention output y
__device__ uint16_t g_Wqh[WELEM], g_Wqm[WELEM];
__device__ uint16_t g_Wkh[WELEM], g_Wkm[WELEM];
__device__ uint16_t g_Wvh[WELEM], g_Wvm[WELEM];
__device__ uint16_t g_Wph[WELEM], g_Wpm[WELEM];

// ---------------- helpers -------------------------------------------------
__device__ __forceinline__ uint32_t pack_bf2(float x1, float x0) {
    uint32_t r;
    asm("cvt.rn.bf16x2.f32 %0, %1, %2;" : "=r"(r) : "f"(x1), "f"(x0));
    return r;
}
// split two floats (x0 = even-k, x1 = odd-k) into packed hi and mid bf16x2
__device__ __forceinline__ uint2 split2(float x0, float x1) {
    uint32_t h = pack_bf2(x1, x0);
    float f0 = __uint_as_float(h << 16);
    float f1 = __uint_as_float(h & 0xffff0000u);
    uint32_t m = pack_bf2(x1 - f1, x0 - f0);
    return make_uint2(h, m);
}
__device__ __forceinline__ void mma_bf16(float* c, const uint32_t* a, const uint32_t* b) {
    asm volatile(
        "mma.sync.aligned.m16n8k16.row.col.f32.bf16.bf16.f32 "
        "{%0,%1,%2,%3}, {%4,%5,%6,%7}, {%8,%9}, {%0,%1,%2,%3};\n"
        : "+f"(c[0]), "+f"(c[1]), "+f"(c[2]), "+f"(c[3])
        : "r"(a[0]), "r"(a[1]), "r"(a[2]), "r"(a[3]), "r"(b[0]), "r"(b[1]));
}
__device__ __forceinline__ void cp16(void* smem_dst, const void* gsrc) {
    unsigned d = (unsigned)__cvta_generic_to_shared(smem_dst);
    asm volatile("cp.async.cg.shared.global [%0], [%1], 16;\n" :: "r"(d), "l"(gsrc));
}
#define CP_COMMIT() asm volatile("cp.async.commit_group;\n")
#define CP_WAIT0()  asm volatile("cp.async.wait_group 0;\n")
#define CP_WAIT1()  asm volatile("cp.async.wait_group 1;\n")
#define CP_WAIT2()  asm volatile("cp.async.wait_group 2;\n")

// =====================================================================
// Split kernels: f32 -> bf16 hi/mid planes
// =====================================================================
#define Q4 ((int)(NELEM / 4))
#define W4 ((int)(WELEM / 4))

__device__ __forceinline__ void split_store(const float4* in, uint32_t* oh, uint32_t* om, int idx) {
    float4 x = in[idx];
    uint2 p0 = split2(x.x, x.y);
    uint2 p1 = split2(x.z, x.w);
    *reinterpret_cast<uint2*>(oh + 2 * idx) = make_uint2(p0.x, p1.x);
    *reinterpret_cast<uint2*>(om + 2 * idx) = make_uint2(p0.y, p1.y);
}

__global__ void __launch_bounds__(256)
split_w_kernel(const float4* __restrict__ Wq, const float4* __restrict__ Wk,
               const float4* __restrict__ Wv, const float4* __restrict__ Wp,
               uint32_t* __restrict__ wqh, uint32_t* __restrict__ wqm,
               uint32_t* __restrict__ wkh, uint32_t* __restrict__ wkm,
               uint32_t* __restrict__ wvh, uint32_t* __restrict__ wvm,
               uint32_t* __restrict__ wph, uint32_t* __restrict__ wpm)
{
    int i = blockIdx.x * blockDim.x + threadIdx.x;
    if (i >= 4 * W4) return;
    if (i < W4)          split_store(Wq, wqh, wqm, i);
    else if (i < 2 * W4) split_store(Wk, wkh, wkm, i - W4);
    else if (i < 3 * W4) split_store(Wv, wvh, wvm, i - 2 * W4);
    else                 split_store(Wp, wph, wpm, i - 3 * W4);
}

__global__ void __launch_bounds__(256)
split_act_kernel(const float4* __restrict__ q, const float4* __restrict__ v,
                 uint32_t* __restrict__ qh, uint32_t* __restrict__ qm,
                 uint32_t* __restrict__ vh, uint32_t* __restrict__ vm)
{
    int i = blockIdx.x * blockDim.x + threadIdx.x;
    if (i >= 2 * Q4) return;
    if (i < Q4) split_store(q, qh, qm, i);
    else        split_store(v, vh, vm, i - Q4);
}

// =====================================================================
// GEMM (round-12 verbatim — best measured 226.8us):
// C[M,N] = A[M,K] @ B[N,K]^T, 3xBF16, 128x128 block, 4 warps (64x64),
// K-chunk 16, 4-stage cp.async pipeline, ONE barrier per chunk.
// mode: 0 -> hi/mid planes row-major; 1 -> V^T planes; 2 -> f32 + bias
// =====================================================================
#define GSW 12                      // words per 16-bf16 row (8 data + 4 pad)
#define GPLANE (128 * GSW)          // 1536 words per plane tile
#define GSTAGE (4 * GPLANE)         // Ah, Am, Bh, Bm = 6144 words = 24KB
#define GNST 4                      // pipeline stages
#define GEMM_SMEM (GNST * GSTAGE * 4)   // 98304 bytes
#define STG_W 133

__global__ void __launch_bounds__(128, 2)
gemm_bf_kernel(const uint16_t* __restrict__ Ah, const uint16_t* __restrict__ Am,
               const uint16_t* __restrict__ Bh, const uint16_t* __restrict__ Bm,
               const float* __restrict__ bias, int mode,
               uint32_t* __restrict__ OH, uint32_t* __restrict__ OM,
               float* __restrict__ OF)
{
    extern __shared__ uint32_t smw[];
    const int t    = threadIdx.x;
    const int warp = t >> 5;
    const int lane = t & 31;
    const int g    = lane >> 2;
    const int tig  = lane & 3;
    const int m0 = blockIdx.y * 128;
    const int n0 = blockIdx.x * 128;
    const int wm = (warp & 1) * 64;
    const int wn = (warp >> 1) * 64;

    auto stage_load = [&](int s, int k0) {
        uint32_t* base = smw + s * GSTAGE;
        const uint16_t* srcs[4] = {
            Ah + (size_t)(m0 + t) * EE + k0, Am + (size_t)(m0 + t) * EE + k0,
            Bh + (size_t)(n0 + t) * EE + k0, Bm + (size_t)(n0 + t) * EE + k0 };
#pragma unroll
        for (int p = 0; p < 4; ++p)
#pragma unroll
            for (int j = 0; j < 2; ++j)
                cp16(base + p * GPLANE + t * GSW + j * 4, srcs[p] + j * 8);
        CP_COMMIT();
    };

    float acc[4][8][4];
#pragma unroll
    for (int mt = 0; mt < 4; ++mt)
#pragma unroll
        for (int nt = 0; nt < 8; ++nt)
#pragma unroll
            for (int r = 0; r < 4; ++r) acc[mt][nt][r] = 0.f;

    stage_load(0, 0);
    stage_load(1, 16);
    stage_load(2, 32);

    const int NCH = EE / 16;   // 64
    for (int c = 0; c < NCH; ++c) {
        if (c + 2 < NCH)      CP_WAIT2();
        else if (c + 1 < NCH) CP_WAIT1();
        else                  CP_WAIT0();
        __syncthreads();      // the ONLY barrier per chunk

        if (c + 3 < NCH) stage_load((c + 3) & (GNST - 1), (c + 3) * 16);

        const uint32_t* S = smw + (c & (GNST - 1)) * GSTAGE;
        uint32_t ah[4][4], am[4][4], bh[8][2], bm[8][2];
#pragma unroll
        for (int mt = 0; mt < 4; ++mt) {
            const int bw = (wm + mt * 16 + g) * GSW + tig;
            ah[mt][0] = S[bw];                ah[mt][1] = S[bw + 8 * GSW];
            ah[mt][2] = S[bw + 4];            ah[mt][3] = S[bw + 8 * GSW + 4];
            am[mt][0] = S[GPLANE + bw];       am[mt][1] = S[GPLANE + bw + 8 * GSW];
            am[mt][2] = S[GPLANE + bw + 4];   am[mt][3] = S[GPLANE + bw + 8 * GSW + 4];
        }
#pragma unroll
        for (int nt = 0; nt < 8; ++nt) {
            const int bw = (wn + nt * 8 + g) * GSW + tig;
            bh[nt][0] = S[2 * GPLANE + bw];   bh[nt][1] = S[2 * GPLANE + bw + 4];
            bm[nt][0] = S[3 * GPLANE + bw];   bm[nt][1] = S[3 * GPLANE + bw + 4];
        }
#pragma unroll
        for (int mt = 0; mt < 4; ++mt)
#pragma unroll
            for (int nt = 0; nt < 8; ++nt)
                mma_bf16(acc[mt][nt], ah[mt], bh[nt]);
#pragma unroll
        for (int mt = 0; mt < 4; ++mt)
#pragma unroll
            for (int nt = 0; nt < 8; ++nt)
                mma_bf16(acc[mt][nt], am[mt], bh[nt]);
#pragma unroll
        for (int mt = 0; mt < 4; ++mt)
#pragma unroll
            for (int nt = 0; nt < 8; ++nt)
                mma_bf16(acc[mt][nt], ah[mt], bm[nt]);
    }
    __syncthreads();   // all warps done reading buffers before staging aliases them

    // ---- epilogue: stage f32 result to smem, then coalesced writes ----
    float* stg = (float*)smw;
#pragma unroll
    for (int mt = 0; mt < 4; ++mt) {
        const int r0 = wm + mt * 16 + g;
#pragma unroll
        for (int nt = 0; nt < 8; ++nt) {
            const int c = wn + nt * 8 + 2 * tig;
            stg[r0 * STG_W + c]           = acc[mt][nt][0];
            stg[r0 * STG_W + c + 1]       = acc[mt][nt][1];
            stg[(r0 + 8) * STG_W + c]     = acc[mt][nt][2];
            stg[(r0 + 8) * STG_W + c + 1] = acc[mt][nt][3];
        }
    }
    __syncthreads();

    if (mode == 0) {            // hi/mid planes, row-major [m][e]
        for (int r = warp; r < 128; r += 4) {
            const size_t o = ((size_t)(m0 + r) * EE + n0) >> 1;   // u32 index
            float x0 = stg[r * STG_W + 2 * lane];
            float x1 = stg[r * STG_W + 2 * lane + 1];
            uint2 p = split2(x0, x1);
            OH[o + lane] = p.x; OM[o + lane] = p.y;
            x0 = stg[r * STG_W + 64 + 2 * lane];
            x1 = stg[r * STG_W + 64 + 2 * lane + 1];
            p = split2(x0, x1);
            OH[o + 32 + lane] = p.x; OM[o + 32 + lane] = p.y;
        }
    } else if (mode == 1) {     // V^T planes: [(b*16+h)*64 + d][t]
        const int b  = m0 >> 11;
        const int t0 = m0 & 2047;
        for (int c = warp; c < 128; c += 4) {
            const int e = n0 + c;
            const int h = e >> 6, d = e & 63;
            const size_t o = ((((size_t)b * HH + h) * DD + d) * TT + t0) >> 1;
            float x0 = stg[(2 * lane) * STG_W + c];
            float x1 = stg[(2 * lane + 1) * STG_W + c];
            uint2 p = split2(x0, x1);
            OH[o + lane] = p.x; OM[o + lane] = p.y;
            x0 = stg[(2 * lane + 64) * STG_W + c];
            x1 = stg[(2 * lane + 65) * STG_W + c];
            p = split2(x0, x1);
            OH[o + 32 + lane] = p.x; OM[o + 32 + lane] = p.y;
        }
    } else {                    // f32 + bias
        for (int r = warp; r < 128; r += 4) {
            const size_t o = (size_t)(m0 + r) * EE + n0;
#pragma unroll
            for (int qd = 0; qd < 4; ++qd) {
                const int c = lane + 32 * qd;
                OF[o + c] = stg[r * STG_W + c] + bias[n0 + c];
            }
        }
    }
}

// =====================================================================
// Flash attention (causal), scale = +sqrt(D) = 8 (faithful quirk)
// 128-row Q tiles, 256 threads / 8 warps (r10-validated mapping);
// 3-stage combined K+V buffers, ONE barrier per key tile, loads 2 ahead.
// =====================================================================
#define ASW 36                       // words per 64-bf16 row (32 data + 4 pad)
#define APLANE (64 * ASW)            // 2304 words
#define ATILE  (2 * APLANE)          // one tile: hi + mid = 4608 words
#define AST    (2 * ATILE)           // stage: K tile + V tile = 9216 words
#define ANST   3                     // pipeline stages
#define ATTN_SMEM (ANST * AST * 4)   // 110592 bytes

// 256-thread tile load: 64 rows x 64 bf16 x 2 planes, 4 cp16/thread
__device__ __forceinline__ void tile_load256(uint32_t* dstw,
                                             const uint16_t* __restrict__ hp,
                                             const uint16_t* __restrict__ mp,
                                             size_t base, int rstride, int t)
{
#pragma unroll
    for (int i = 0; i < 4; ++i) {
        const int idx = t + i * 256;
        const int p   = idx >> 9;
        const int rem = idx & 511;
        const int row = rem >> 3;
        const int ch  = rem & 7;
        const uint16_t* src = (p ? mp : hp) + base + (size_t)row * rstride + ch * 8;
        cp16(dstw + p * APLANE + row * ASW + ch * 4, src);
    }
}

__global__ void __launch_bounds__(256, 1)
attn_kernel(const uint16_t* __restrict__ qph, const uint16_t* __restrict__ qpm,
            const uint16_t* __restrict__ kph, const uint16_t* __restrict__ kpm,
            const uint16_t* __restrict__ vth, const uint16_t* __restrict__ vtm,
            uint32_t* __restrict__ YH, uint32_t* __restrict__ YM)
{
    extern __shared__ uint32_t smw[];

    const int qi = (TT / 128 - 1) - blockIdx.x;   // heavy tiles first
    const int bh = blockIdx.y;
    const int b  = bh >> 4;
    const int h  = bh & 15;
    const int t  = threadIdx.x;
    const int warp = t >> 5, lane = t & 31;
    const int g = lane >> 2, tig = lane & 3;
    const int wq = warp * 16;                 // warp's q-row offset within 128

    const size_t qbase  = ((size_t)b * TT + (size_t)qi * 128) * EE + h * DD;
    const size_t kbase  = ((size_t)b * TT) * EE + h * DD;
    const size_t vtbase = (((size_t)b * HH + h) * DD) * TT;

    // ---- Q tile (128 rows) -> registers: stage halves in stage0/stage1 K areas
    tile_load256(smw,           qph, qpm, qbase, EE, t);                   // rows 0-63
    tile_load256(smw + AST,     qph, qpm, qbase + (size_t)64 * EE, EE, t); // rows 64-127
    CP_COMMIT(); CP_WAIT0();
    __syncthreads();

    uint32_t qAh[4][4], qAm[4][4];
    {
        const uint32_t* sQ = smw + (warp < 4 ? 0 : AST);
        const int rq = (warp & 3) * 16;
#pragma unroll
        for (int kt = 0; kt < 4; ++kt) {
            const int bw = (rq + g) * ASW + kt * 8 + tig;
            qAh[kt][0] = sQ[bw];               qAh[kt][1] = sQ[bw + 8 * ASW];
            qAh[kt][2] = sQ[bw + 4];           qAh[kt][3] = sQ[bw + 8 * ASW + 4];
            qAm[kt][0] = sQ[APLANE + bw];      qAm[kt][1] = sQ[APLANE + bw + 8 * ASW];
            qAm[kt][2] = sQ[APLANE + bw + 4];  qAm[kt][3] = sQ[APLANE + bw + 8 * ASW + 4];
        }
    }
    __syncthreads();   // all warps done with Q staging before KV loads overwrite

    float m_r[2] = {-INFINITY, -INFINITY};
    float l_r[2] = {0.f, 0.f};
    float yacc[8][4];
#pragma unroll
    for (int nt = 0; nt < 8; ++nt)
#pragma unroll
        for (int r = 0; r < 4; ++r) yacc[nt][r] = 0.f;

    const int NJ = 2 * qi + 2;     // 64-key tiles covering causal range

    // KV stage load: K tile + V tile as ONE group
    auto kv_load = [&](int s, int j) {
        uint32_t* dst = smw + s * AST;
        tile_load256(dst,         kph, kpm, kbase + (size_t)j * 64 * EE, EE, t);
        tile_load256(dst + ATILE, vth, vtm, vtbase + (size_t)j * 64, TT, t);
        CP_COMMIT();
    };

    // preload up to 2 stages (prefetch depth 2)
    kv_load(0, 0);
    if (1 < NJ) kv_load(1, 1);

    for (int j = 0; j < NJ; ++j) {
        // groups committed so far: min(NJ, j+2); need KV[j] complete
        if (j + 2 < NJ + 1 && (j + 2) <= NJ - 1 + 1 && (j + 2) < NJ + 1) {}
        if ((j + 2) <= NJ - 1) CP_WAIT1();   // KV[j+1] still allowed in flight
        else                   CP_WAIT0();
        __syncthreads();      // the ONLY barrier per key tile

        // issue KV[j+2] into buffer (j+2)%3 == (j-1)%3 (safe: all warps past
        // this barrier => everyone finished reading buffer (j-1) last iter)
        if (j + 2 < NJ) kv_load((j + 2) % ANST, j + 2);

        const uint32_t* stK = smw + (j % ANST) * AST;
        const uint32_t* stV = stK + ATILE;

        // ---- S = Q K^T (16x64 per warp), bf16x3 ----
        float s[8][4];
#pragma unroll
        for (int nt = 0; nt < 8; ++nt)
#pragma unroll
            for (int r = 0; r < 4; ++r) s[nt][r] = 0.f;
#pragma unroll
        for (int kt = 0; kt < 4; ++kt) {
            uint32_t kh[8][2], km[8][2];
#pragma unroll
            for (int nt = 0; nt < 8; ++nt) {
                const int bw = (nt * 8 + g) * ASW + kt * 8 + tig;
                kh[nt][0] = stK[bw];          kh[nt][1] = stK[bw + 4];
                km[nt][0] = stK[APLANE + bw]; km[nt][1] = stK[APLANE + bw + 4];
            }
#pragma unroll
            for (int nt = 0; nt < 8; ++nt) mma_bf16(s[nt], qAh[kt], kh[nt]);
#pragma unroll
            for (int nt = 0; nt < 8; ++nt) mma_bf16(s[nt], qAm[kt], kh[nt]);
#pragma unroll
            for (int nt = 0; nt < 8; ++nt) mma_bf16(s[nt], qAh[kt], km[nt]);
        }

        // ---- scale (+mask near diagonal); scale = +sqrt(D) quirk ----
        const float scale = 8.0f;
        const int warp_row0 = qi * 128 + wq;
        if (j * 64 + 63 <= warp_row0) {               // whole warp unmasked
#pragma unroll
            for (int nt = 0; nt < 8; ++nt)
#pragma unroll
                for (int r = 0; r < 4; ++r) s[nt][r] *= scale;
        } else {
            const int r0 = warp_row0 + g, r1 = warp_row0 + g + 8;
#pragma unroll
            for (int nt = 0; nt < 8; ++nt) {
                const int c = j * 64 + nt * 8 + 2 * tig;
                s[nt][0] = (c     <= r0) ? s[nt][0] * scale : -INFINITY;
                s[nt][1] = (c + 1 <= r0) ? s[nt][1] * scale : -INFINITY;
                s[nt][2] = (c     <= r1) ? s[nt][2] * scale : -INFINITY;
                s[nt][3] = (c + 1 <= r1) ? s[nt][3] * scale : -INFINITY;
            }
        }

        // ---- online softmax per row-half ----
#pragma unroll
        for (int half = 0; half < 2; ++half) {
            float mx = -INFINITY;
#pragma unroll
            for (int nt = 0; nt < 8; ++nt)
                mx = fmaxf(mx, fmaxf(s[nt][half * 2], s[nt][half * 2 + 1]));
            mx = fmaxf(mx, __shfl_xor_sync(0xffffffffu, mx, 1));
            mx = fmaxf(mx, __shfl_xor_sync(0xffffffffu, mx, 2));
            const float mnew  = fmaxf(m_r[half], mx);
            const float alpha = __expf(m_r[half] - mnew);
            float rs = 0.f;
#pragma unroll
            for (int nt = 0; nt < 8; ++nt) {
                float p0 = __expf(s[nt][half * 2]     - mnew);
                float p1 = __expf(s[nt][half * 2 + 1] - mnew);
                s[nt][half * 2]     = p0;
                s[nt][half * 2 + 1] = p1;
                rs += p0 + p1;
            }
            rs += __shfl_xor_sync(0xffffffffu, rs, 1);
            rs += __shfl_xor_sync(0xffffffffu, rs, 2);
            l_r[half] = l_r[half] * alpha + rs;
            m_r[half] = mnew;
#pragma unroll
            for (int nt = 0; nt < 8; ++nt) {
                yacc[nt][half * 2]     *= alpha;
                yacc[nt][half * 2 + 1] *= alpha;
            }
        }

        // ---- Y += P @ V : P built in-register (no smem round-trip) ----
#pragma unroll
        for (int kt = 0; kt < 4; ++kt) {
            uint32_t ph[4], pm[4];
            uint2 p;
            p = split2(s[2 * kt][0],     s[2 * kt][1]);     ph[0] = p.x; pm[0] = p.y;
            p = split2(s[2 * kt][2],     s[2 * kt][3]);     ph[1] = p.x; pm[1] = p.y;
            p = split2(s[2 * kt + 1][0], s[2 * kt + 1][1]); ph[2] = p.x; pm[2] = p.y;
            p = split2(s[2 * kt + 1][2], s[2 * kt + 1][3]); ph[3] = p.x; pm[3] = p.y;
            uint32_t vh[8][2], vm[8][2];
#pragma unroll
            for (int nt = 0; nt < 8; ++nt) {
                const int bw = (nt * 8 + g) * ASW + kt * 8 + tig;
                vh[nt][0] = stV[bw];          vh[nt][1] = stV[bw + 4];
                vm[nt][0] = stV[APLANE + bw]; vm[nt][1] = stV[APLANE + bw + 4];
            }
#pragma unroll
            for (int nt = 0; nt < 8; ++nt) mma_bf16(yacc[nt], ph, vh[nt]);
#pragma unroll
            for (int nt = 0; nt < 8; ++nt) mma_bf16(yacc[nt], pm, vh[nt]);
#pragma unroll
            for (int nt = 0; nt < 8; ++nt) mma_bf16(yacc[nt], ph, vm[nt]);
        }
    }

    // ---- finalize: divide by l, write hi/mid planes (paired u32 stores) ----
    const float inv0 = 1.f / l_r[0];
    const float inv1 = 1.f / l_r[1];
    const size_t o0 = qbase + (size_t)(wq + g) * EE;
    const size_t o1 = qbase + (size_t)(wq + g + 8) * EE;
#pragma unroll
    for (int nt = 0; nt < 8; ++nt) {
        const int c = nt * 8 + 2 * tig;
        uint2 p = split2(yacc[nt][0] * inv0, yacc[nt][1] * inv0);
        YH[(o0 + c) >> 1] = p.x; YM[(o0 + c) >> 1] = p.y;
        p = split2(yacc[nt][2] * inv1, yacc[nt][3] * inv1);
        YH[(o1 + c) >> 1] = p.x; YM[(o1 + c) >> 1] = p.y;
    }
}

// =====================================================================
// Host launcher
// =====================================================================
extern "C" void kernel_launch(void* const* d_in, const int* in_sizes, int n_in,
                              void* d_out, int out_size)
{
    (void)in_sizes; (void)n_in; (void)out_size;
    const float* q  = (const float*)d_in[0];
    // d_in[1] = external k: UNUSED (reference computes kp from qp — faithful quirk)
    const float* v  = (const float*)d_in[2];
    const float* Wq = (const float*)d_in[3];
    const float* Wk = (const float*)d_in[4];
    const float* Wv = (const float*)d_in[5];
    const float* Wp = (const float*)d_in[6];
    const float* bp = (const float*)d_in[7];
    float* out = (float*)d_out;

    uint16_t *qh,*qm,*vh,*vm,*qph,*qpm,*kph,*kpm,*vth,*vtm,*yh,*ym;
    uint16_t *Wqh,*Wqm,*Wkh,*Wkm,*Wvh,*Wvm,*Wph,*Wpm;
    cudaGetSymbolAddress((void**)&qh,  g_qh);  cudaGetSymbolAddress((void**)&qm,  g_qm);
    cudaGetSymbolAddress((void**)&vh,  g_vh);  cudaGetSymbolAddress((void**)&vm,  g_vm);
    cudaGetSymbolAddress((void**)&qph, g_qph); cudaGetSymbolAddress((void**)&qpm, g_qpm);
    cudaGetSymbolAddress((void**)&kph, g_kph); cudaGetSymbolAddress((void**)&kpm, g_kpm);
    cudaGetSymbolAddress((void**)&vth, g_vth); cudaGetSymbolAddress((void**)&vtm, g_vtm);
    cudaGetSymbolAddress((void**)&yh,  g_yh);  cudaGetSymbolAddress((void**)&ym,  g_ym);
    cudaGetSymbolAddress((void**)&Wqh, g_Wqh); cudaGetSymbolAddress((void**)&Wqm, g_Wqm);
    cudaGetSymbolAddress((void**)&Wkh, g_Wkh); cudaGetSymbolAddress((void**)&Wkm, g_Wkm);
    cudaGetSymbolAddress((void**)&Wvh, g_Wvh); cudaGetSymbolAddress((void**)&Wvm, g_Wvm);
    cudaGetSymbolAddress((void**)&Wph, g_Wph); cudaGetSymbolAddress((void**)&Wpm, g_Wpm);

    cudaFuncSetAttribute(gemm_bf_kernel, cudaFuncAttributeMaxDynamicSharedMemorySize, GEMM_SMEM);
    cudaFuncSetAttribute(attn_kernel,    cudaFuncAttributeMaxDynamicSharedMemorySize, ATTN_SMEM);

    // 0) weight splits
    split_w_kernel<<<(4 * W4 + 255) / 256, 256>>>(
        (const float4*)Wq, (const float4*)Wk, (const float4*)Wv, (const float4*)Wp,
        (uint32_t*)Wqh, (uint32_t*)Wqm, (uint32_t*)Wkh, (uint32_t*)Wkm,
        (uint32_t*)Wvh, (uint32_t*)Wvm, (uint32_t*)Wph, (uint32_t*)Wpm);
    // 1) activation splits
    split_act_kernel<<<(2 * Q4 + 255) / 256, 256>>>(
        (const float4*)q, (const float4*)v,
        (uint32_t*)qh, (uint32_t*)qm, (uint32_t*)vh, (uint32_t*)vm);

    const dim3 ggrd(EE / 128, MM / 128);   // (8, 64)

    // 2) qp = q @ Wq^T  -> planes
    gemm_bf_kernel<<<ggrd, 128, GEMM_SMEM>>>(qh, qm, Wqh, Wqm, nullptr, 0,
                                             (uint32_t*)qph, (uint32_t*)qpm, nullptr);
    // 3) kp = qp @ Wk^T (faithful quirk) -> planes
    gemm_bf_kernel<<<ggrd, 128, GEMM_SMEM>>>(qph, qpm, Wkh, Wkm, nullptr, 0,
                                             (uint32_t*)kph, (uint32_t*)kpm, nullptr);
    // 4) vp = v @ Wv^T  -> V^T planes
    gemm_bf_kernel<<<ggrd, 128, GEMM_SMEM>>>(vh, vm, Wvh, Wvm, nullptr, 1,
                                             (uint32_t*)vth, (uint32_t*)vtm, nullptr);
    // 5) causal flash attention (128-row Q tiles, single-barrier 3-stage KV)
    attn_kernel<<<dim3(TT / 128, BB * HH), 256, ATTN_SMEM>>>(
        qph, qpm, kph, kpm, vth, vtm, (uint32_t*)yh, (uint32_t*)ym);
    // 6) out = y @ Wp^T + bp (f32)
    gemm_bf_kernel<<<ggrd, 128, GEMM_SMEM>>>(yh, ym, Wph, Wpm, bp, 2,
                                             nullptr, nullptr, out);
}

// round 17
// speedup vs baseline: 1.1156x; 1.1156x over previous
#include <cuda_runtime.h>
#include <cuda_bf16.h>
#include <cstdint>

// Problem constants
#define BB 4
#define TT 2048
#define EE 1024
#define HH 16
#define DD 64
#define MM (BB*TT)                 // 8192
#define NELEM ((size_t)MM * EE)    // 8388608
#define WELEM ((size_t)EE * EE)    // 1048576

// ---------------- scratch: bf16 hi/mid planes (no runtime alloc) ----------
__device__ uint16_t g_qh [NELEM], g_qm [NELEM];   // split of input q
__device__ uint16_t g_vh [NELEM], g_vm [NELEM];   // split of input v
__device__ uint16_t g_qph[NELEM], g_qpm[NELEM];   // qp (row-major)
__device__ uint16_t g_kph[NELEM], g_kpm[NELEM];   // kp (row-major)
__device__ uint16_t g_vth[NELEM], g_vtm[NELEM];   // vp TRANSPOSED: [(b,h,d)][t]
__device__ uint16_t g_yh [NELEM], g_ym [NELEM];   // attention output y
__device__ uint16_t g_Wqh[WELEM], g_Wqm[WELEM];
__device__ uint16_t g_Wkh[WELEM], g_Wkm[WELEM];
__device__ uint16_t g_Wvh[WELEM], g_Wvm[WELEM];
__device__ uint16_t g_Wph[WELEM], g_Wpm[WELEM];

// ---------------- helpers -------------------------------------------------
__device__ __forceinline__ uint32_t pack_bf2(float x1, float x0) {
    uint32_t r;
    asm("cvt.rn.bf16x2.f32 %0, %1, %2;" : "=r"(r) : "f"(x1), "f"(x0));
    return r;
}
// split two floats (x0 = even-k, x1 = odd-k) into packed hi and mid bf16x2
__device__ __forceinline__ uint2 split2(float x0, float x1) {
    uint32_t h = pack_bf2(x1, x0);
    float f0 = __uint_as_float(h << 16);
    float f1 = __uint_as_float(h & 0xffff0000u);
    uint32_t m = pack_bf2(x1 - f1, x0 - f0);
    return make_uint2(h, m);
}
__device__ __forceinline__ void mma_bf16(float* c, const uint32_t* a, const uint32_t* b) {
    asm volatile(
        "mma.sync.aligned.m16n8k16.row.col.f32.bf16.bf16.f32 "
        "{%0,%1,%2,%3}, {%4,%5,%6,%7}, {%8,%9}, {%0,%1,%2,%3};\n"
        : "+f"(c[0]), "+f"(c[1]), "+f"(c[2]), "+f"(c[3])
        : "r"(a[0]), "r"(a[1]), "r"(a[2]), "r"(a[3]), "r"(b[0]), "r"(b[1]));
}
__device__ __forceinline__ void cp16(void* smem_dst, const void* gsrc) {
    unsigned d = (unsigned)__cvta_generic_to_shared(smem_dst);
    asm volatile("cp.async.cg.shared.global [%0], [%1], 16;\n" :: "r"(d), "l"(gsrc));
}
#define CP_COMMIT() asm volatile("cp.async.commit_group;\n")
#define CP_WAIT0()  asm volatile("cp.async.wait_group 0;\n")
#define CP_WAIT1()  asm volatile("cp.async.wait_group 1;\n")
#define CP_WAIT2()  asm volatile("cp.async.wait_group 2;\n")

// =====================================================================
// Fused split kernel: all six f32 inputs -> bf16 hi/mid planes
// =====================================================================
#define Q4 ((int)(NELEM / 4))
#define W4 ((int)(WELEM / 4))
#define SPLIT_TOTAL4 (2 * Q4 + 4 * W4)

__device__ __forceinline__ void split_store(const float4* in, uint32_t* oh, uint32_t* om, int idx) {
    float4 x = in[idx];
    uint2 p0 = split2(x.x, x.y);
    uint2 p1 = split2(x.z, x.w);
    *reinterpret_cast<uint2*>(oh + 2 * idx) = make_uint2(p0.x, p1.x);
    *reinterpret_cast<uint2*>(om + 2 * idx) = make_uint2(p0.y, p1.y);
}

__global__ void __launch_bounds__(256)
split_all_kernel(const float4* __restrict__ q,  const float4* __restrict__ v,
                 const float4* __restrict__ Wq, const float4* __restrict__ Wk,
                 const float4* __restrict__ Wv, const float4* __restrict__ Wp,
                 uint32_t* __restrict__ qh,  uint32_t* __restrict__ qm,
                 uint32_t* __restrict__ vh,  uint32_t* __restrict__ vm,
                 uint32_t* __restrict__ wqh, uint32_t* __restrict__ wqm,
                 uint32_t* __restrict__ wkh, uint32_t* __restrict__ wkm,
                 uint32_t* __restrict__ wvh, uint32_t* __restrict__ wvm,
                 uint32_t* __restrict__ wph, uint32_t* __restrict__ wpm)
{
    int i = blockIdx.x * blockDim.x + threadIdx.x;
    if (i >= SPLIT_TOTAL4) return;
    if (i < Q4)                     split_store(q,  qh,  qm,  i);
    else if (i < 2 * Q4)            split_store(v,  vh,  vm,  i - Q4);
    else if (i < 2 * Q4 + W4)       split_store(Wq, wqh, wqm, i - 2 * Q4);
    else if (i < 2 * Q4 + 2 * W4)   split_store(Wk, wkh, wkm, i - 2 * Q4 - W4);
    else if (i < 2 * Q4 + 3 * W4)   split_store(Wv, wvh, wvm, i - 2 * Q4 - 2 * W4);
    else                            split_store(Wp, wph, wpm, i - 2 * Q4 - 3 * W4);
}

// =====================================================================
// GEMM (round-12 mainloop verbatim — best measured 226.8us):
// C[M,N] = A[M,K] @ B[N,K]^T, 3xBF16, 128x128 block, 4 warps (64x64),
// K-chunk 16, 4-stage cp.async pipeline, ONE barrier per chunk.
// blockIdx.z selects input/output set (fused independent GEMMs).
// mode: 0 -> hi/mid planes row-major; 1 -> V^T planes; 2 -> f32 + bias
// =====================================================================
#define GSW 12                      // words per 16-bf16 row (8 data + 4 pad)
#define GPLANE (128 * GSW)          // 1536 words per plane tile
#define GSTAGE (4 * GPLANE)         // Ah, Am, Bh, Bm = 6144 words = 24KB
#define GNST 4                      // pipeline stages
#define GEMM_SMEM (GNST * GSTAGE * 4)   // 98304 bytes
#define STG_W 133

__global__ void __launch_bounds__(128, 2)
gemm_bf_kernel(const uint16_t* __restrict__ Ah0, const uint16_t* __restrict__ Am0,
               const uint16_t* __restrict__ Bh0, const uint16_t* __restrict__ Bm0,
               int mode0, uint32_t* __restrict__ OH0, uint32_t* __restrict__ OM0,
               const uint16_t* __restrict__ Ah1, const uint16_t* __restrict__ Am1,
               const uint16_t* __restrict__ Bh1, const uint16_t* __restrict__ Bm1,
               int mode1, uint32_t* __restrict__ OH1, uint32_t* __restrict__ OM1,
               const float* __restrict__ bias, float* __restrict__ OF)
{
    extern __shared__ uint32_t smw[];
    const int t    = threadIdx.x;
    const int warp = t >> 5;
    const int lane = t & 31;
    const int g    = lane >> 2;
    const int tig  = lane & 3;
    const int m0 = blockIdx.y * 128;
    const int n0 = blockIdx.x * 128;
    const int wm = (warp & 1) * 64;
    const int wn = (warp >> 1) * 64;

    // select parameter set (z-fused independent GEMMs)
    const bool z1 = (blockIdx.z == 1);
    const uint16_t* Ah = z1 ? Ah1 : Ah0;
    const uint16_t* Am = z1 ? Am1 : Am0;
    const uint16_t* Bh = z1 ? Bh1 : Bh0;
    const uint16_t* Bm = z1 ? Bm1 : Bm0;
    uint32_t* OH = z1 ? OH1 : OH0;
    uint32_t* OM = z1 ? OM1 : OM0;
    const int mode = z1 ? mode1 : mode0;

    auto stage_load = [&](int s, int k0) {
        uint32_t* base = smw + s * GSTAGE;
        const uint16_t* srcs[4] = {
            Ah + (size_t)(m0 + t) * EE + k0, Am + (size_t)(m0 + t) * EE + k0,
            Bh + (size_t)(n0 + t) * EE + k0, Bm + (size_t)(n0 + t) * EE + k0 };
#pragma unroll
        for (int p = 0; p < 4; ++p)
#pragma unroll
            for (int j = 0; j < 2; ++j)
                cp16(base + p * GPLANE + t * GSW + j * 4, srcs[p] + j * 8);
        CP_COMMIT();
    };

    float acc[4][8][4];
#pragma unroll
    for (int mt = 0; mt < 4; ++mt)
#pragma unroll
        for (int nt = 0; nt < 8; ++nt)
#pragma unroll
            for (int r = 0; r < 4; ++r) acc[mt][nt][r] = 0.f;

    stage_load(0, 0);
    stage_load(1, 16);
    stage_load(2, 32);

    const int NCH = EE / 16;   // 64
    for (int c = 0; c < NCH; ++c) {
        if (c + 2 < NCH)      CP_WAIT2();
        else if (c + 1 < NCH) CP_WAIT1();
        else                  CP_WAIT0();
        __syncthreads();      // the ONLY barrier per chunk

        if (c + 3 < NCH) stage_load((c + 3) & (GNST - 1), (c + 3) * 16);

        const uint32_t* S = smw + (c & (GNST - 1)) * GSTAGE;
        uint32_t ah[4][4], am[4][4], bh[8][2], bm[8][2];
#pragma unroll
        for (int mt = 0; mt < 4; ++mt) {
            const int bw = (wm + mt * 16 + g) * GSW + tig;
            ah[mt][0] = S[bw];                ah[mt][1] = S[bw + 8 * GSW];
            ah[mt][2] = S[bw + 4];            ah[mt][3] = S[bw + 8 * GSW + 4];
            am[mt][0] = S[GPLANE + bw];       am[mt][1] = S[GPLANE + bw + 8 * GSW];
            am[mt][2] = S[GPLANE + bw + 4];   am[mt][3] = S[GPLANE + bw + 8 * GSW + 4];
        }
#pragma unroll
        for (int nt = 0; nt < 8; ++nt) {
            const int bw = (wn + nt * 8 + g) * GSW + tig;
            bh[nt][0] = S[2 * GPLANE + bw];   bh[nt][1] = S[2 * GPLANE + bw + 4];
            bm[nt][0] = S[3 * GPLANE + bw];   bm[nt][1] = S[3 * GPLANE + bw + 4];
        }
#pragma unroll
        for (int mt = 0; mt < 4; ++mt)
#pragma unroll
            for (int nt = 0; nt < 8; ++nt)
                mma_bf16(acc[mt][nt], ah[mt], bh[nt]);
#pragma unroll
        for (int mt = 0; mt < 4; ++mt)
#pragma unroll
            for (int nt = 0; nt < 8; ++nt)
                mma_bf16(acc[mt][nt], am[mt], bh[nt]);
#pragma unroll
        for (int mt = 0; mt < 4; ++mt)
#pragma unroll
            for (int nt = 0; nt < 8; ++nt)
                mma_bf16(acc[mt][nt], ah[mt], bm[nt]);
    }
    __syncthreads();   // all warps done reading buffers before staging aliases them

    // ---- epilogue: stage f32 result to smem, then coalesced writes ----
    float* stg = (float*)smw;
#pragma unroll
    for (int mt = 0; mt < 4; ++mt) {
        const int r0 = wm + mt * 16 + g;
#pragma unroll
        for (int nt = 0; nt < 8; ++nt) {
            const int c = wn + nt * 8 + 2 * tig;
            stg[r0 * STG_W + c]           = acc[mt][nt][0];
            stg[r0 * STG_W + c + 1]       = acc[mt][nt][1];
            stg[(r0 + 8) * STG_W + c]     = acc[mt][nt][2];
            stg[(r0 + 8) * STG_W + c + 1] = acc[mt][nt][3];
        }
    }
    __syncthreads();

    if (mode == 0) {            // hi/mid planes, row-major [m][e]
        for (int r = warp; r < 128; r += 4) {
            const size_t o = ((size_t)(m0 + r) * EE + n0) >> 1;   // u32 index
            float x0 = stg[r * STG_W + 2 * lane];
            float x1 = stg[r * STG_W + 2 * lane + 1];
            uint2 p = split2(x0, x1);
            OH[o + lane] = p.x; OM[o + lane] = p.y;
            x0 = stg[r * STG_W + 64 + 2 * lane];
            x1 = stg[r * STG_W + 64 + 2 * lane + 1];
            p = split2(x0, x1);
            OH[o + 32 + lane] = p.x; OM[o + 32 + lane] = p.y;
        }
    } else if (mode == 1) {     // V^T planes: [(b*16+h)*64 + d][t]
        const int b  = m0 >> 11;
        const int t0 = m0 & 2047;
        for (int c = warp; c < 128; c += 4) {
            const int e = n0 + c;
            const int h = e >> 6, d = e & 63;
            const size_t o = ((((size_t)b * HH + h) * DD + d) * TT + t0) >> 1;
            float x0 = stg[(2 * lane) * STG_W + c];
            float x1 = stg[(2 * lane + 1) * STG_W + c];
            uint2 p = split2(x0, x1);
            OH[o + lane] = p.x; OM[o + lane] = p.y;
            x0 = stg[(2 * lane + 64) * STG_W + c];
            x1 = stg[(2 * lane + 65) * STG_W + c];
            p = split2(x0, x1);
            OH[o + 32 + lane] = p.x; OM[o + 32 + lane] = p.y;
        }
    } else {                    // f32 + bias
        for (int r = warp; r < 128; r += 4) {
            const size_t o = (size_t)(m0 + r) * EE + n0;
#pragma unroll
            for (int qd = 0; qd < 4; ++qd) {
                const int c = lane + 32 * qd;
                OF[o + c] = stg[r * STG_W + c] + bias[n0 + c];
            }
        }
    }
}

// =====================================================================
// Flash attention (round-12 verbatim): causal, scale = +sqrt(D) = 8,
// bf16x3 mma, 64x64 tiles, 4 warps, 2 CTAs/SM; P stays in registers
// =====================================================================
#define ASW 36                       // words per 64-bf16 row (32 data + 4 pad)
#define APLANE (64 * ASW)            // 2304 words
#define ATILE  (2 * APLANE)          // hi + mid
#define ATTN_SMEM (2 * ATILE * 4)    // sK + sV = 36864 bytes

__device__ __forceinline__ void tile_load(uint32_t* dstw,
                                          const uint16_t* __restrict__ hp,
                                          const uint16_t* __restrict__ mp,
                                          size_t base, int rstride, int t)
{
#pragma unroll
    for (int i = 0; i < 8; ++i) {
        const int idx = t + i * 128;
        const int p   = idx >> 9;
        const int rem = idx & 511;
        const int row = rem >> 3;
        const int ch  = rem & 7;
        const uint16_t* src = (p ? mp : hp) + base + (size_t)row * rstride + ch * 8;
        cp16(dstw + p * APLANE + row * ASW + ch * 4, src);
    }
}

__global__ void __launch_bounds__(128, 2)
attn_kernel(const uint16_t* __restrict__ qph, const uint16_t* __restrict__ qpm,
            const uint16_t* __restrict__ kph, const uint16_t* __restrict__ kpm,
            const uint16_t* __restrict__ vth, const uint16_t* __restrict__ vtm,
            uint32_t* __restrict__ YH, uint32_t* __restrict__ YM)
{
    extern __shared__ uint32_t smw[];
    uint32_t* sK = smw;            // K tile (hi+mid), also Q staging
    uint32_t* sV = smw + ATILE;    // V^T tile (hi+mid)

    const int qi = (TT / 64 - 1) - blockIdx.x;   // heavy tiles first
    const int bh = blockIdx.y;
    const int b  = bh >> 4;
    const int h  = bh & 15;
    const int t  = threadIdx.x;
    const int warp = t >> 5, lane = t & 31;
    const int g = lane >> 2, tig = lane & 3;
    const int wq = warp * 16;

    const size_t qbase  = ((size_t)b * TT + (size_t)qi * 64) * EE + h * DD;
    const size_t vtbase = (((size_t)b * HH + h) * DD) * TT;

    // ---- Q tile -> registers (through sK staging) ----
    tile_load(sK, qph, qpm, qbase, EE, t);
    CP_COMMIT(); CP_WAIT0();
    __syncthreads();

    uint32_t qAh[4][4], qAm[4][4];
#pragma unroll
    for (int kt = 0; kt < 4; ++kt) {
        const int bw = (wq + g) * ASW + kt * 8 + tig;
        qAh[kt][0] = sK[bw];               qAh[kt][1] = sK[bw + 8 * ASW];
        qAh[kt][2] = sK[bw + 4];           qAh[kt][3] = sK[bw + 8 * ASW + 4];
        qAm[kt][0] = sK[APLANE + bw];      qAm[kt][1] = sK[APLANE + bw + 8 * ASW];
        qAm[kt][2] = sK[APLANE + bw + 4];  qAm[kt][3] = sK[APLANE + bw + 8 * ASW + 4];
    }
    __syncthreads();

    float m_r[2] = {-INFINITY, -INFINITY};
    float l_r[2] = {0.f, 0.f};
    float yacc[8][4];
#pragma unroll
    for (int nt = 0; nt < 8; ++nt)
#pragma unroll
        for (int r = 0; r < 4; ++r) yacc[nt][r] = 0.f;

    // preload K[0]
    tile_load(sK, kph, kpm, ((size_t)b * TT) * EE + h * DD, EE, t);
    CP_COMMIT();

    for (int j = 0; j <= qi; ++j) {
        CP_WAIT0();          // K[j] arrived
        __syncthreads();     // visible to all; all warps done PV[j-1]

        tile_load(sV, vth, vtm, vtbase + (size_t)j * 64, TT, t);   // V[j] overlaps S
        CP_COMMIT();

        // ---- S = Q K^T (16x64 per warp), bf16x3 ----
        float s[8][4];
#pragma unroll
        for (int nt = 0; nt < 8; ++nt)
#pragma unroll
            for (int r = 0; r < 4; ++r) s[nt][r] = 0.f;
#pragma unroll
        for (int kt = 0; kt < 4; ++kt) {
            uint32_t kh[8][2], km[8][2];
#pragma unroll
            for (int nt = 0; nt < 8; ++nt) {
                const int bw = (nt * 8 + g) * ASW + kt * 8 + tig;
                kh[nt][0] = sK[bw];          kh[nt][1] = sK[bw + 4];
                km[nt][0] = sK[APLANE + bw]; km[nt][1] = sK[APLANE + bw + 4];
            }
#pragma unroll
            for (int nt = 0; nt < 8; ++nt) mma_bf16(s[nt], qAh[kt], kh[nt]);
#pragma unroll
            for (int nt = 0; nt < 8; ++nt) mma_bf16(s[nt], qAm[kt], kh[nt]);
#pragma unroll
            for (int nt = 0; nt < 8; ++nt) mma_bf16(s[nt], qAh[kt], km[nt]);
        }

        CP_WAIT0();          // V[j] arrived
        __syncthreads();     // all warps done with sK

        if (j < qi) tile_load(sK, kph, kpm, ((size_t)b * TT + (size_t)(j + 1) * 64) * EE + h * DD, EE, t);
        CP_COMMIT();

        // ---- scale (+mask on diagonal tile); scale = +sqrt(D) quirk ----
        const float scale = 8.0f;
        if (j == qi) {
            const int r0 = wq + g, r1 = wq + g + 8;
#pragma unroll
            for (int nt = 0; nt < 8; ++nt) {
                const int c = nt * 8 + 2 * tig;
                s[nt][0] = (c     <= r0) ? s[nt][0] * scale : -INFINITY;
                s[nt][1] = (c + 1 <= r0) ? s[nt][1] * scale : -INFINITY;
                s[nt][2] = (c     <= r1) ? s[nt][2] * scale : -INFINITY;
                s[nt][3] = (c + 1 <= r1) ? s[nt][3] * scale : -INFINITY;
            }
        } else {
#pragma unroll
            for (int nt = 0; nt < 8; ++nt)
#pragma unroll
                for (int r = 0; r < 4; ++r) s[nt][r] *= scale;
        }

        // ---- online softmax per row-half ----
#pragma unroll
        for (int half = 0; half < 2; ++half) {
            float mx = -INFINITY;
#pragma unroll
            for (int nt = 0; nt < 8; ++nt)
                mx = fmaxf(mx, fmaxf(s[nt][half * 2], s[nt][half * 2 + 1]));
            mx = fmaxf(mx, __shfl_xor_sync(0xffffffffu, mx, 1));
            mx = fmaxf(mx, __shfl_xor_sync(0xffffffffu, mx, 2));
            const float mnew  = fmaxf(m_r[half], mx);
            const float alpha = __expf(m_r[half] - mnew);
            float rs = 0.f;
#pragma unroll
            for (int nt = 0; nt < 8; ++nt) {
                float p0 = __expf(s[nt][half * 2]     - mnew);
                float p1 = __expf(s[nt][half * 2 + 1] - mnew);
                s[nt][half * 2]     = p0;
                s[nt][half * 2 + 1] = p1;
                rs += p0 + p1;
            }
            rs += __shfl_xor_sync(0xffffffffu, rs, 1);
            rs += __shfl_xor_sync(0xffffffffu, rs, 2);
            l_r[half] = l_r[half] * alpha + rs;
            m_r[half] = mnew;
#pragma unroll
            for (int nt = 0; nt < 8; ++nt) {
                yacc[nt][half * 2]     *= alpha;
                yacc[nt][half * 2 + 1] *= alpha;
            }
        }

        // ---- Y += P @ V : P built in-register (no smem round-trip) ----
#pragma unroll
        for (int kt = 0; kt < 4; ++kt) {
            uint32_t ph[4], pm[4];
            uint2 p;
            p = split2(s[2 * kt][0],     s[2 * kt][1]);     ph[0] = p.x; pm[0] = p.y;
            p = split2(s[2 * kt][2],     s[2 * kt][3]);     ph[1] = p.x; pm[1] = p.y;
            p = split2(s[2 * kt + 1][0], s[2 * kt + 1][1]); ph[2] = p.x; pm[2] = p.y;
            p = split2(s[2 * kt + 1][2], s[2 * kt + 1][3]); ph[3] = p.x; pm[3] = p.y;
            uint32_t vh[8][2], vm[8][2];
#pragma unroll
            for (int nt = 0; nt < 8; ++nt) {
                const int bw = (nt * 8 + g) * ASW + kt * 8 + tig;
                vh[nt][0] = sV[bw];          vh[nt][1] = sV[bw + 4];
                vm[nt][0] = sV[APLANE + bw]; vm[nt][1] = sV[APLANE + bw + 4];
            }
#pragma unroll
            for (int nt = 0; nt < 8; ++nt) mma_bf16(yacc[nt], ph, vh[nt]);
#pragma unroll
            for (int nt = 0; nt < 8; ++nt) mma_bf16(yacc[nt], pm, vh[nt]);
#pragma unroll
            for (int nt = 0; nt < 8; ++nt) mma_bf16(yacc[nt], ph, vm[nt]);
        }
    }

    // ---- finalize: divide by l, write hi/mid planes (paired u32 stores) ----
    const float inv0 = 1.f / l_r[0];
    const float inv1 = 1.f / l_r[1];
    const size_t o0 = qbase + (size_t)(wq + g) * EE;
    const size_t o1 = qbase + (size_t)(wq + g + 8) * EE;
#pragma unroll
    for (int nt = 0; nt < 8; ++nt) {
        const int c = nt * 8 + 2 * tig;
        uint2 p = split2(yacc[nt][0] * inv0, yacc[nt][1] * inv0);
        YH[(o0 + c) >> 1] = p.x; YM[(o0 + c) >> 1] = p.y;
        p = split2(yacc[nt][2] * inv1, yacc[nt][3] * inv1);
        YH[(o1 + c) >> 1] = p.x; YM[(o1 + c) >> 1] = p.y;
    }
}

// =====================================================================
// Host launcher — 5 launches (split fused; qp+vp GEMMs z-fused)
// =====================================================================
extern "C" void kernel_launch(void* const* d_in, const int* in_sizes, int n_in,
                              void* d_out, int out_size)
{
    (void)in_sizes; (void)n_in; (void)out_size;
    const float* q  = (const float*)d_in[0];
    // d_in[1] = external k: UNUSED (reference computes kp from qp — faithful quirk)
    const float* v  = (const float*)d_in[2];
    const float* Wq = (const float*)d_in[3];
    const float* Wk = (const float*)d_in[4];
    const float* Wv = (const float*)d_in[5];
    const float* Wp = (const float*)d_in[6];
    const float* bp = (const float*)d_in[7];
    float* out = (float*)d_out;

    uint16_t *qh,*qm,*vh,*vm,*qph,*qpm,*kph,*kpm,*vth,*vtm,*yh,*ym;
    uint16_t *Wqh,*Wqm,*Wkh,*Wkm,*Wvh,*Wvm,*Wph,*Wpm;
    cudaGetSymbolAddress((void**)&qh,  g_qh);  cudaGetSymbolAddress((void**)&qm,  g_qm);
    cudaGetSymbolAddress((void**)&vh,  g_vh);  cudaGetSymbolAddress((void**)&vm,  g_vm);
    cudaGetSymbolAddress((void**)&qph, g_qph); cudaGetSymbolAddress((void**)&qpm, g_qpm);
    cudaGetSymbolAddress((void**)&kph, g_kph); cudaGetSymbolAddress((void**)&kpm, g_kpm);
    cudaGetSymbolAddress((void**)&vth, g_vth); cudaGetSymbolAddress((void**)&vtm, g_vtm);
    cudaGetSymbolAddress((void**)&yh,  g_yh);  cudaGetSymbolAddress((void**)&ym,  g_ym);
    cudaGetSymbolAddress((void**)&Wqh, g_Wqh); cudaGetSymbolAddress((void**)&Wqm, g_Wqm);
    cudaGetSymbolAddress((void**)&Wkh, g_Wkh); cudaGetSymbolAddress((void**)&Wkm, g_Wkm);
    cudaGetSymbolAddress((void**)&Wvh, g_Wvh); cudaGetSymbolAddress((void**)&Wvm, g_Wvm);
    cudaGetSymbolAddress((void**)&Wph, g_Wph); cudaGetSymbolAddress((void**)&Wpm, g_Wpm);

    cudaFuncSetAttribute(gemm_bf_kernel, cudaFuncAttributeMaxDynamicSharedMemorySize, GEMM_SMEM);
    cudaFuncSetAttribute(attn_kernel,    cudaFuncAttributeMaxDynamicSharedMemorySize, ATTN_SMEM);

    // 0) one fused split for all six inputs
    split_all_kernel<<<(SPLIT_TOTAL4 + 255) / 256, 256>>>(
        (const float4*)q, (const float4*)v,
        (const float4*)Wq, (const float4*)Wk, (const float4*)Wv, (const float4*)Wp,
        (uint32_t*)qh, (uint32_t*)qm, (uint32_t*)vh, (uint32_t*)vm,
        (uint32_t*)Wqh, (uint32_t*)Wqm, (uint32_t*)Wkh, (uint32_t*)Wkm,
        (uint32_t*)Wvh, (uint32_t*)Wvm, (uint32_t*)Wph, (uint32_t*)Wpm);

    const dim3 ggrd1(EE / 128, MM / 128, 1);   // (8, 64, 1)
    const dim3 ggrd2(EE / 128, MM / 128, 2);   // (8, 64, 2) fused qp + vp

    // 1) FUSED: z=0: qp = q @ Wq^T -> planes; z=1: vp = v @ Wv^T -> V^T planes
    gemm_bf_kernel<<<ggrd2, 128, GEMM_SMEM>>>(
        qh, qm, Wqh, Wqm, 0, (uint32_t*)qph, (uint32_t*)qpm,
        vh, vm, Wvh, Wvm, 1, (uint32_t*)vth, (uint32_t*)vtm,
        nullptr, nullptr);
    // 2) kp = qp @ Wk^T (faithful quirk) -> planes
    gemm_bf_kernel<<<ggrd1, 128, GEMM_SMEM>>>(
        qph, qpm, Wkh, Wkm, 0, (uint32_t*)kph, (uint32_t*)kpm,
        qph, qpm, Wkh, Wkm, 0, (uint32_t*)kph, (uint32_t*)kpm,
        nullptr, nullptr);
    // 3) causal flash attention (r12 verbatim)
    attn_kernel<<<dim3(TT / 64, BB * HH), 128, ATTN_SMEM>>>(
        qph, qpm, kph, kpm, vth, vtm, (uint32_t*)yh, (uint32_t*)ym);
    // 4) out = y @ Wp^T + bp (f32)
    gemm_bf_kernel<<<ggrd1, 128, GEMM_SMEM>>>(
        yh, ym, Wph, Wpm, 2, nullptr, nullptr,
        yh, ym, Wph, Wpm, 2, nullptr, nullptr,
        bp, out);
}